// round 16
// baseline (speedup 1.0000x reference)
#include <cuda_runtime.h>
#include <cuda_bf16.h>
#include <cstdint>

#define BATCH 4096
#define DIM 512
#define TWOB 8192
#define INV_TEMP 10.0f

// ---------------- scratch (no allocations allowed) ----------------
__device__ __nv_bfloat16 g_z[(size_t)TWOB * DIM];   // normalized rows, bf16 [8192,512]
__device__ float g_pos[BATCH];                      // cos(n1_i, n2_i)
__device__ float g_rowsum[TWOB];                    // sum_{j!=i} exp(cos_ij/T)

// ---------------- helpers ----------------
__device__ __forceinline__ uint32_t smem_u32(const void* p) {
    uint32_t a;
    asm("{ .reg .u64 t; cvta.to.shared.u64 t, %1; cvt.u32.u64 %0, t; }" : "=r"(a) : "l"(p));
    return a;
}
__device__ __forceinline__ void cp16(uint32_t s, const void* g) {
    asm volatile("cp.async.cg.shared.global [%0], [%1], 16;" :: "r"(s), "l"(g) : "memory");
}
__device__ __forceinline__ void ldm_x4(uint32_t& r0, uint32_t& r1, uint32_t& r2, uint32_t& r3,
                                       uint32_t addr) {
    asm volatile("ldmatrix.sync.aligned.m8n8.x4.shared.b16 {%0,%1,%2,%3}, [%4];"
                 : "=r"(r0), "=r"(r1), "=r"(r2), "=r"(r3) : "r"(addr));
}
__device__ __forceinline__ void mma_16816(float* d, const uint32_t* a, const uint32_t* b) {
    asm volatile(
        "mma.sync.aligned.m16n8k16.row.col.f32.bf16.bf16.f32 "
        "{%0,%1,%2,%3}, {%4,%5,%6,%7}, {%8,%9}, {%0,%1,%2,%3};"
        : "+f"(d[0]), "+f"(d[1]), "+f"(d[2]), "+f"(d[3])
        : "r"(a[0]), "r"(a[1]), "r"(a[2]), "r"(a[3]), "r"(b[0]), "r"(b[1]));
}
// pack two floats -> bf16x2 as raw u32 (header-version-proof)
__device__ __forceinline__ uint32_t pack_bf16x2(float lo, float hi) {
    __nv_bfloat162 v = __floats2bfloat162_rn(lo, hi);
    uint32_t u;
    asm("mov.b32 %0, %1;" : "=r"(u) : "r"(*reinterpret_cast<uint32_t*>(&v)));
    return u;
}

// tile geometry
#define BM 128
#define BN 128
#define BK 32
#define NSTEPS (DIM / BK)          // 16
#define NT (TWOB / BM)             // 64 tile-rows
#define NTILES (NT * (NT + 1) / 2) // 2080 upper-triangle tiles
#define TILE_BYTES (BM * BK * 2)   // 8192 per operand tile
#define STAGE_BYTES (2 * TILE_BYTES)
#define NSTAGE 4
#define SMEM_BYTES (NSTAGE * STAGE_BYTES)   // 64 KB dynamic (x2 CTAs = 128 KB/SM)

// swizzled byte offset inside a [rows x 32cols bf16] tile (64B rows, 4 x 16B chunks)
__device__ __forceinline__ uint32_t swz(int row, int chunk) {
    return (uint32_t)(row * 64 + ((chunk ^ ((row >> 1) & 3)) << 4));
}

// ============ Kernel A: persistent warp-per-row L2-normalize, positives, init ============
// grid-stride over rows: overlaps next row's loads with current row's stores,
// amortizes launch ramp; 2 CTAs/SM.
__global__ void __launch_bounds__(128) k_norm(const float* __restrict__ p1,
                                              const float* __restrict__ p2,
                                              float* __restrict__ out,
                                              int nwarps_total) {
    const int lane = threadIdx.x & 31;
    const int gwarp = blockIdx.x * 4 + (threadIdx.x >> 5);
    if (blockIdx.x == 0 && threadIdx.x == 0) out[0] = 0.f;  // init output accumulator

    for (int row = gwarp; row < BATCH; row += nwarps_total) {
        const float4* A = (const float4*)(p1 + (size_t)row * DIM);
        const float4* B = (const float4*)(p2 + (size_t)row * DIM);
        float4 a[4], b[4];
#pragma unroll
        for (int j = 0; j < 4; j++) a[j] = A[j * 32 + lane];
#pragma unroll
        for (int j = 0; j < 4; j++) b[j] = B[j * 32 + lane];

        float sa = 0.f, sb = 0.f, dp = 0.f;
#pragma unroll
        for (int j = 0; j < 4; j++) {
            sa += a[j].x * a[j].x + a[j].y * a[j].y + a[j].z * a[j].z + a[j].w * a[j].w;
            sb += b[j].x * b[j].x + b[j].y * b[j].y + b[j].z * b[j].z + b[j].w * b[j].w;
            dp += a[j].x * b[j].x + a[j].y * b[j].y + a[j].z * b[j].z + a[j].w * b[j].w;
        }
#pragma unroll
        for (int o = 16; o; o >>= 1) {
            sa += __shfl_xor_sync(0xffffffffu, sa, o);
            sb += __shfl_xor_sync(0xffffffffu, sb, o);
            dp += __shfl_xor_sync(0xffffffffu, dp, o);
        }
        const float ra = rsqrtf(fmaxf(sa, 1e-24f));
        const float rb = rsqrtf(fmaxf(sb, 1e-24f));

        if (!lane) {
            g_pos[row] = dp * ra * rb;    // cos of raw vectors == dot of normalized
            g_rowsum[row] = 0.f;
            g_rowsum[BATCH + row] = 0.f;
        }

        uint2* Z1 = (uint2*)(g_z + (size_t)row * DIM);
        uint2* Z2 = (uint2*)(g_z + (size_t)(BATCH + row) * DIM);
#pragma unroll
        for (int j = 0; j < 4; j++) {
            uint2 pa, pb;
            pa.x = pack_bf16x2(a[j].x * ra, a[j].y * ra);
            pa.y = pack_bf16x2(a[j].z * ra, a[j].w * ra);
            pb.x = pack_bf16x2(b[j].x * rb, b[j].y * rb);
            pb.y = pack_bf16x2(b[j].z * rb, b[j].w * rb);
            Z1[j * 32 + lane] = pa;
            Z2[j * 32 + lane] = pb;
        }
    }
}

// ============ Kernel B: persistent (static-stride) bf16 GEMM + exp + row/col sums ====
// EXACT R7 pipeline: 4-stage ring, wait_group 2, producer 3 ahead across tiles, 2 CTAs/SM.
__global__ void __launch_bounds__(128, 2) k_sim() {
    extern __shared__ __align__(128) char smem[];
    const uint32_t sbase = smem_u32(smem);

    const int tid = threadIdx.x;
    const int lane = tid & 31;
    const int wid = tid >> 5;
    const int warp_m = wid & 1;
    const int warp_n = wid >> 1;

    auto tile_of = [](int bid, int& ti, int& tj) {
        auto offs = [](int t) { return t * NT - (t * (t - 1)) / 2; };
        int x = (int)((2.f * NT + 1.f -
                       sqrtf((2.f * NT + 1.f) * (2.f * NT + 1.f) - 8.f * bid)) * 0.5f);
        if (x < 0) x = 0;
        if (x > NT - 1) x = NT - 1;
        while (offs(x + 1) <= bid) x++;
        while (offs(x) > bid) x--;
        ti = x;
        tj = x + (bid - offs(x));
    };

    auto load_stage = [&](const __nv_bfloat16* pza, const __nv_bfloat16* pzb,
                          int kc, int buf) {
        const uint32_t sA = sbase + buf * STAGE_BYTES;
        const uint32_t sB = sA + TILE_BYTES;
#pragma unroll
        for (int it = 0; it < 8; it++) {
            int id = it * 128 + tid;
            int tile = id >> 9;
            int idx = id & 511;
            int row = idx >> 2, ch = idx & 3;
            const __nv_bfloat16* g = (tile ? pzb : pza) + (size_t)row * DIM + kc * BK + ch * 8;
            cp16((tile ? sB : sA) + swz(row, ch), g);
        }
        asm volatile("cp.async.commit_group;" ::: "memory");
    };

    // ldmatrix lane address components
    const int a_row = warp_m * 64 + (lane & 15);
    const int a_chsel = lane >> 4;
    const int b_row = warp_n * 64 + (lane & 7) + ((lane >> 4) << 3);
    const int b_chsel = (lane >> 3) & 1;

    int t = blockIdx.x;
    if (t >= NTILES) return;
    int ti, tj;
    tile_of(t, ti, tj);
    const __nv_bfloat16* za = g_z + (size_t)ti * BM * DIM;
    const __nv_bfloat16* zb = g_z + (size_t)tj * BN * DIM;

    int pbuf = 3, cbuf = 0;
    load_stage(za, zb, 0, 0);
    load_stage(za, zb, 1, 1);
    load_stage(za, zb, 2, 2);

    while (true) {
        // next tile (wrap for the final iteration: redundant loads, harmless)
        int t2 = t + gridDim.x;
        int nti, ntj;
        tile_of(t2 < NTILES ? t2 : t, nti, ntj);
        const __nv_bfloat16* nza = g_z + (size_t)nti * BM * DIM;
        const __nv_bfloat16* nzb = g_z + (size_t)ntj * BN * DIM;

        float acc[4][8][4];
#pragma unroll
        for (int mt = 0; mt < 4; mt++)
#pragma unroll
            for (int nt = 0; nt < 8; nt++)
#pragma unroll
                for (int c = 0; c < 4; c++) acc[mt][nt][c] = 0.f;

        for (int kc = 0; kc < NSTEPS; kc++) {
            asm volatile("cp.async.wait_group 2;" ::: "memory");
            __syncthreads();
            {   // producer: stage kc+3 (this tile or the next)
                int s = kc + 3;
                if (s < NSTEPS) load_stage(za, zb, s, pbuf);
                else            load_stage(nza, nzb, s - NSTEPS, pbuf);
                pbuf = (pbuf == NSTAGE - 1) ? 0 : pbuf + 1;
            }
            const uint32_t sA = sbase + cbuf * STAGE_BYTES;
            const uint32_t sB = sA + TILE_BYTES;
            cbuf = (cbuf == NSTAGE - 1) ? 0 : cbuf + 1;

#pragma unroll
            for (int ks = 0; ks < 2; ks++) {
                uint32_t a[4][4];
#pragma unroll
                for (int mt = 0; mt < 4; mt++)
                    ldm_x4(a[mt][0], a[mt][1], a[mt][2], a[mt][3],
                           sA + swz(a_row + mt * 16, ks * 2 + a_chsel));
#pragma unroll
                for (int p = 0; p < 4; p++) {
                    uint32_t b[4];
                    ldm_x4(b[0], b[1], b[2], b[3],
                           sB + swz(b_row + p * 16, ks * 2 + b_chsel));
#pragma unroll
                    for (int mt = 0; mt < 4; mt++) {
                        mma_16816(acc[mt][p * 2],     a[mt], b);
                        mma_16816(acc[mt][p * 2 + 1], a[mt], b + 2);
                    }
                }
            }
        }

        // ---------------- epilogue: exp + row/col sums (producer already 3 ahead) ----
        const bool diag = (ti == tj);
        const int row0 = ti * BM + warp_m * 64 + (lane >> 2);
        const int col0 = tj * BN + warp_n * 64 + (lane & 3) * 2;
        float rs[4][2] = {{0.f,0.f},{0.f,0.f},{0.f,0.f},{0.f,0.f}};

        if (diag) {
#pragma unroll
            for (int mt = 0; mt < 4; mt++)
#pragma unroll
                for (int nt = 0; nt < 8; nt++)
#pragma unroll
                    for (int c = 0; c < 4; c++) {
                        int grow = row0 + mt * 16 + (c >> 1) * 8;
                        int gcol = col0 + nt * 8 + (c & 1);
                        float e = __expf(acc[mt][nt][c] * INV_TEMP);
                        rs[mt][c >> 1] += (grow == gcol) ? 0.f : e;
                    }
        } else {
            float cs[8][2];
#pragma unroll
            for (int nt = 0; nt < 8; nt++) { cs[nt][0] = 0.f; cs[nt][1] = 0.f; }
#pragma unroll
            for (int mt = 0; mt < 4; mt++)
#pragma unroll
                for (int nt = 0; nt < 8; nt++)
#pragma unroll
                    for (int c = 0; c < 4; c++) {
                        float e = __expf(acc[mt][nt][c] * INV_TEMP);
                        rs[mt][c >> 1] += e;
                        cs[nt][c & 1] += e;
                    }
#pragma unroll
            for (int o = 4; o <= 16; o <<= 1)
#pragma unroll
                for (int nt = 0; nt < 8; nt++) {
                    cs[nt][0] += __shfl_xor_sync(0xffffffffu, cs[nt][0], o);
                    cs[nt][1] += __shfl_xor_sync(0xffffffffu, cs[nt][1], o);
                }
            if (lane < 4) {
                const int cbase = tj * BN + warp_n * 64 + lane * 2;
#pragma unroll
                for (int nt = 0; nt < 8; nt++) {
                    atomicAdd(&g_rowsum[cbase + nt * 8],     cs[nt][0]);
                    atomicAdd(&g_rowsum[cbase + nt * 8 + 1], cs[nt][1]);
                }
            }
        }
#pragma unroll
        for (int o = 1; o <= 2; o <<= 1)
#pragma unroll
            for (int mt = 0; mt < 4; mt++)
#pragma unroll
                for (int h = 0; h < 2; h++)
                    rs[mt][h] += __shfl_xor_sync(0xffffffffu, rs[mt][h], o);
        if ((lane & 3) == 0) {
#pragma unroll
            for (int mt = 0; mt < 4; mt++)
#pragma unroll
                for (int h = 0; h < 2; h++)
                    atomicAdd(&g_rowsum[row0 + mt * 16 + h * 8], rs[mt][h]);
        }

        if (t2 >= NTILES) break;
        t = t2; ti = nti; tj = ntj; za = nza; zb = nzb;
    }
    asm volatile("cp.async.wait_group 0;" ::: "memory");
}

// ============ Kernel C: parallel final reduction (32 blocks -> d_out atomic) ============
__global__ void __launch_bounds__(256) k_red(float* __restrict__ out) {
    const int tid = blockIdx.x * 256 + threadIdx.x;   // 8192 threads total
    float v = __logf(g_rowsum[tid]);
    if (tid < BATCH) v -= 2.f * INV_TEMP * g_pos[tid];
#pragma unroll
    for (int o = 16; o; o >>= 1) v += __shfl_xor_sync(0xffffffffu, v, o);
    __shared__ float sh[8];
    if (!(threadIdx.x & 31)) sh[threadIdx.x >> 5] = v;
    __syncthreads();
    if (threadIdx.x < 8) {
        float s = sh[threadIdx.x];
#pragma unroll
        for (int o = 4; o; o >>= 1) s += __shfl_xor_sync(0xffu, s, o);
        if (!threadIdx.x) atomicAdd(out, s * (1.f / (float)TWOB));
    }
}

extern "C" void kernel_launch(void* const* d_in, const int* in_sizes, int n_in,
                              void* d_out, int out_size) {
    const float* p1 = (const float*)d_in[0];
    const float* p2 = (const float*)d_in[1];
    int nsm = 148;
    cudaDeviceGetAttribute(&nsm, cudaDevAttrMultiProcessorCount, 0);
    int grid = 2 * nsm;
    if (grid > NTILES) grid = NTILES;
    cudaFuncSetAttribute(k_sim, cudaFuncAttributeMaxDynamicSharedMemorySize, SMEM_BYTES);
    int ngrid = 2 * nsm;                 // persistent k_norm: 2 CTAs/SM
    k_norm<<<ngrid, 128>>>(p1, p2, (float*)d_out, ngrid * 4);
    k_sim<<<grid, 128, SMEM_BYTES>>>();
    k_red<<<TWOB / 256, 256>>>((float*)d_out);
}